// round 12
// baseline (speedup 1.0000x reference)
#include <cuda_runtime.h>
#include <cuda_bf16.h>
#include <mma.h>
#include <cstdint>

using namespace nvcuda;

// ---------------- problem constants ----------------
#define B_    2
#define S_    2048
#define DIM_  5120
#define H_    40
#define KVH_  8
#define HD_   128
#define NREP_ 5
#define M_    (B_*S_)        // 4096
#define KVDIM_ (KVH_*HD_)    // 1024
#define QKV_N (DIM_ + 2*KVDIM_)   // 7168
#define WINDOW_ 1024
static const float SCALE_F = (float)(1.2079441541679836 / 11.313708498984760390); // mscale / sqrt(128)

// ---------------- scratch (device globals; no allocations allowed) ----------------
__device__ __align__(256) float g_xr  [(size_t)M_*DIM_];       // tf32-RN-rounded x
__device__ __align__(256) float g_w1  [(size_t)DIM_*QKV_N];    // tf32-RN-rounded concat(wq|wk|wv)
__device__ __align__(256) float g_wo_r[(size_t)DIM_*DIM_];     // tf32-RN-rounded wo
__device__ __align__(256) float g_xqkv[(size_t)M_*QKV_N];      // QKV projection output
__device__ __align__(256) float g_q [(size_t)B_*H_*S_*HD_];    // tf32-RN-rounded
__device__ __align__(256) float g_k [(size_t)B_*KVH_*S_*HD_];  // tf32-RN-rounded
__device__ __align__(256) float g_v [(size_t)B_*KVH_*S_*HD_];  // tf32-RN-rounded
__device__ __align__(256) float g_attn[(size_t)M_*DIM_];       // tf32-RN-rounded attention out

__device__ __forceinline__ void cp_async16(void* dst_smem, const void* src_gmem)
{
    uint32_t d = (uint32_t)__cvta_generic_to_shared(dst_smem);
    asm volatile("cp.async.cg.shared.global [%0], [%1], 16;" :: "r"(d), "l"(src_gmem) : "memory");
}
#define CP_COMMIT() asm volatile("cp.async.commit_group;" ::: "memory")
#define CP_WAIT1()  asm volatile("cp.async.wait_group 1;" ::: "memory")

// ================= tf32 WMMA GEMM, 3-stage cp.async pipeline, BK=32 =================
// C[M,N] = A[M,K] @ B[K,N], row-major fp32. Inputs MUST be pre-rounded to tf32-RN.
// CTA tile 128x128, BK=32, 3 stages -> 35,328 B/stage, 105,984 B total => 2 CTAs/SM.
// Fragment loads double-buffered in registers across kk-steps.
#define BKQ  32
#define BKP  36          // A leading dim; 144 B/row, 16B-aligned
#define BNP  132         // B leading dim; 528 B/row, 16B-aligned
#define A_STG_F (128*BKP)            // 4608 floats
#define B_STG_F (BKQ*BNP)            // 4224 floats
#define STG_F   (A_STG_F + B_STG_F)  // 8832 floats
#define NSTAGE  3
#define GEMM_SMEM (NSTAGE*STG_F*4)   // 105,984 B

__global__ __launch_bounds__(256, 2) void gemm_tf32(const float* __restrict__ A,
                                                    const float* __restrict__ Bm,
                                                    float* __restrict__ C,
                                                    int N, int K)
{
    extern __shared__ float smem[];
    const int tid = threadIdx.x;
    const int w   = tid >> 5;
    const int wm  = w & 3;      // 0..3 -> 32-row slab
    const int wn  = w >> 2;     // 0..1 -> 64-col slab
    const int bm0 = blockIdx.y * 128;
    const int bn0 = blockIdx.x * 128;
    const int NK  = K >> 5;     // K/32 steps

    wmma::fragment<wmma::accumulator, 16, 16, 8, float> acc[2][4];
    #pragma unroll
    for (int i = 0; i < 2; i++)
        #pragma unroll
        for (int j = 0; j < 4; j++)
            wmma::fill_fragment(acc[i][j], 0.0f);

    // stage loader: 2048 x 16B chunks (A: 1024, B: 1024), 8 per thread
    auto issue_stage = [&](int s, int k0) {
        float* as = smem + s * STG_F;
        float* bs = as + A_STG_F;
        #pragma unroll
        for (int t = 0; t < 8; t++) {
            int idx = tid + t * 256;
            if (idx < 1024) {                      // A: 128 rows x 8 chunks
                int m = idx >> 3, c = (idx & 7) << 2;
                cp_async16(as + m * BKP + c, A + (size_t)(bm0 + m) * K + k0 + c);
            } else {                               // B: 32 k-rows x 32 chunks
                int j = idx - 1024;
                int kr = j >> 5, c = (j & 31) << 2;
                cp_async16(bs + kr * BNP + c, Bm + (size_t)(k0 + kr) * N + bn0 + c);
            }
        }
    };

    issue_stage(0, 0);
    CP_COMMIT();
    issue_stage(1, BKQ);
    CP_COMMIT();

    for (int i = 0; i < NK; i++) {
        CP_WAIT1();
        __syncthreads();

        // issue the next stage FIRST so the copy overlaps this stage's MMAs
        const int nx = i + 2;
        if (nx < NK) issue_stage(nx % NSTAGE, nx * BKQ);
        CP_COMMIT();

        const float* as = smem + (i % NSTAGE) * STG_F;
        const float* bs = as + A_STG_F;

        wmma::fragment<wmma::matrix_a, 16, 16, 8, wmma::precision::tf32, wmma::row_major> af[2][2];
        wmma::fragment<wmma::matrix_b, 16, 16, 8, wmma::precision::tf32, wmma::row_major> bf[2][4];
        #pragma unroll
        for (int x = 0; x < 2; x++)
            wmma::load_matrix_sync(af[0][x], as + (wm * 32 + x * 16) * BKP, BKP);
        #pragma unroll
        for (int j = 0; j < 4; j++)
            wmma::load_matrix_sync(bf[0][j], bs + wn * 64 + j * 16, BNP);

        #pragma unroll
        for (int kt = 0; kt < 4; kt++) {
            const int cur = kt & 1, nxt = cur ^ 1;
            if (kt < 3) {                          // prefetch kk+8 fragments
                const int kk = (kt + 1) * 8;
                #pragma unroll
                for (int x = 0; x < 2; x++)
                    wmma::load_matrix_sync(af[nxt][x], as + (wm * 32 + x * 16) * BKP + kk, BKP);
                #pragma unroll
                for (int j = 0; j < 4; j++)
                    wmma::load_matrix_sync(bf[nxt][j], bs + kk * BNP + wn * 64 + j * 16, BNP);
            }
            #pragma unroll
            for (int x = 0; x < 2; x++)
                #pragma unroll
                for (int j = 0; j < 4; j++)
                    wmma::mma_sync(acc[x][j], af[cur][x], bf[cur][j], acc[x][j]);
        }
    }

    #pragma unroll
    for (int x = 0; x < 2; x++)
        #pragma unroll
        for (int j = 0; j < 4; j++)
            wmma::store_matrix_sync(C + (size_t)(bm0 + wm * 32 + x * 16) * N + bn0 + wn * 64 + j * 16,
                                    acc[x][j], N, wmma::mem_row_major);
}

// ================= tf32-RN rounding passes =================
__global__ __launch_bounds__(256) void round_copy(float* __restrict__ dst,
                                                  const float* __restrict__ src, int n4)
{
    int i = blockIdx.x * 256 + threadIdx.x;
    if (i >= n4) return;
    float4 v = ((const float4*)src)[i];
    float4 o;
    o.x = wmma::__float_to_tf32(v.x); o.y = wmma::__float_to_tf32(v.y);
    o.z = wmma::__float_to_tf32(v.z); o.w = wmma::__float_to_tf32(v.w);
    ((float4*)dst)[i] = o;
}

__global__ __launch_bounds__(256) void round_concat_w(const float* __restrict__ wq,
                                                      const float* __restrict__ wk,
                                                      const float* __restrict__ wv)
{
    int i = blockIdx.x * 256 + threadIdx.x;        // float4 index into [5120, 7168]
    const int n4 = DIM_ * QKV_N / 4;
    if (i >= n4) return;
    int c = (i % (QKV_N / 4)) * 4;
    int d = i / (QKV_N / 4);
    const float* src;
    if (c < DIM_)                 src = wq + (size_t)d * DIM_   + c;
    else if (c < DIM_ + KVDIM_)   src = wk + (size_t)d * KVDIM_ + (c - DIM_);
    else                          src = wv + (size_t)d * KVDIM_ + (c - DIM_ - KVDIM_);
    float4 v = *(const float4*)src;
    float4 o;
    o.x = wmma::__float_to_tf32(v.x); o.y = wmma::__float_to_tf32(v.y);
    o.z = wmma::__float_to_tf32(v.z); o.w = wmma::__float_to_tf32(v.w);
    ((float4*)g_w1)[i] = o;
}

// ---------------- block sum helper ----------------
__device__ __forceinline__ float block_sum_256(float v, float* red8)
{
    #pragma unroll
    for (int o = 16; o > 0; o >>= 1) v += __shfl_xor_sync(0xffffffffu, v, o);
    if ((threadIdx.x & 31) == 0) red8[threadIdx.x >> 5] = v;
    __syncthreads();
    float total = 0.0f;
    #pragma unroll
    for (int i = 0; i < 8; i++) total += red8[i];
    return total;
}

// ---------------- RMSNorm(5120) + RoPE on Q, re-layout to [b,h,s,d], tf32-RN ----------------
__global__ __launch_bounds__(256) void qnorm_rope_kernel(const float* __restrict__ qw,
                                                         const float* __restrict__ cos_h,
                                                         const float* __restrict__ sin_h)
{
    __shared__ float red8[8];
    const int row = blockIdx.x;
    const int b = row >> 11;
    const int s = row & (S_ - 1);
    const float* xr = g_xqkv + (size_t)row * QKV_N;

    float ss = 0.0f;
    for (int i = threadIdx.x; i < DIM_; i += 256) { float v = xr[i]; ss += v * v; }
    float total = block_sum_256(ss, red8);
    const float rms = rsqrtf(total / (float)DIM_ + 1e-6f);

    for (int idx = threadIdx.x; idx < H_ * 64; idx += 256) {
        int h = idx >> 6;
        int d = idx & 63;
        float x1 = xr[h * HD_ + d]      * rms * qw[h * HD_ + d];
        float x2 = xr[h * HD_ + d + 64] * rms * qw[h * HD_ + d + 64];
        float c  = cos_h[s * 64 + d];
        float sn = sin_h[s * 64 + d];
        float* o = g_q + ((size_t)(b * H_ + h) * S_ + s) * HD_;
        o[d]      = wmma::__float_to_tf32(x1 * c - x2 * sn);
        o[d + 64] = wmma::__float_to_tf32(x2 * c + x1 * sn);
    }
}

// ---------------- RMSNorm(1024) + RoPE on K, copy/relayout V, tf32-RN ----------------
__global__ __launch_bounds__(256) void knorm_rope_v_kernel(const float* __restrict__ kw,
                                                           const float* __restrict__ cos_h,
                                                           const float* __restrict__ sin_h)
{
    __shared__ float red8[8];
    const int row = blockIdx.x;
    const int b = row >> 11;
    const int s = row & (S_ - 1);
    const float* xk = g_xqkv + (size_t)row * QKV_N + DIM_;
    const float* xv = g_xqkv + (size_t)row * QKV_N + DIM_ + KVDIM_;

    float ss = 0.0f;
    for (int i = threadIdx.x; i < KVDIM_; i += 256) { float v = xk[i]; ss += v * v; }
    float total = block_sum_256(ss, red8);
    const float rms = rsqrtf(total / (float)KVDIM_ + 1e-6f);

    for (int idx = threadIdx.x; idx < KVH_ * 64; idx += 256) {
        int h = idx >> 6;
        int d = idx & 63;
        float x1 = xk[h * HD_ + d]      * rms * kw[h * HD_ + d];
        float x2 = xk[h * HD_ + d + 64] * rms * kw[h * HD_ + d + 64];
        float c  = cos_h[s * 64 + d];
        float sn = sin_h[s * 64 + d];
        float* o = g_k + ((size_t)(b * KVH_ + h) * S_ + s) * HD_;
        o[d]      = wmma::__float_to_tf32(x1 * c - x2 * sn);
        o[d + 64] = wmma::__float_to_tf32(x2 * c + x1 * sn);
    }
    for (int idx = threadIdx.x; idx < KVDIM_; idx += 256) {
        int h = idx >> 7;
        int d = idx & 127;
        g_v[((size_t)(b * KVH_ + h) * S_ + s) * HD_ + d] = wmma::__float_to_tf32(xv[idx]);
    }
}

// ---------------- flash attention: cp.async double-buffered K/V, WMMA tf32 ----------------
#define QT 64
#define KT 64
#define HDP 132
#define STP 72
#define TILE_F (QT * HDP)                          // 8448 floats
#define ATT_SMEM_FLOATS (6 * TILE_F + QT * STP + 3 * QT)
#define ATT_SMEM_BYTES  (ATT_SMEM_FLOATS * 4)      // 221,952 B

__global__ __launch_bounds__(256) void attn_kernel()
{
    extern __shared__ float sm[];
    float* Qs  = sm;                  // 64 x 132
    float* Ks0 = Qs + TILE_F;         // 2 x (64 x 132)
    float* Vs0 = Ks0 + 2 * TILE_F;    // 2 x (64 x 132)
    float* Os  = Vs0 + 2 * TILE_F;    // 64 x 132
    float* Ss  = Os + TILE_F;         // 64 x 72
    float* m_s = Ss + QT * STP;
    float* l_s = m_s + QT;
    float* al_s = l_s + QT;

    const int q0  = blockIdx.x * QT;
    const int h   = blockIdx.y;
    const int b   = blockIdx.z;
    const int kvh = h / NREP_;
    const int tid = threadIdx.x;
    const int w   = tid >> 5;
    const int wm  = w & 3;
    const int wn  = w >> 2;

    const float* Qg = g_q + ((size_t)(b * H_ + h) * S_ + q0) * HD_;
    const float* Kg = g_k + ((size_t)(b * KVH_ + kvh) * S_) * HD_;
    const float* Vg = g_v + ((size_t)(b * KVH_ + kvh) * S_) * HD_;

    auto issue_kv = [&](int buf, int j0) {
        float* ks = Ks0 + buf * TILE_F;
        float* vs = Vs0 + buf * TILE_F;
        #pragma unroll
        for (int t = 0; t < 16; t++) {
            int idx = tid + t * 256;
            int r = (idx >> 5) & 63, c = (idx & 31) << 2;
            if (idx < 2048) cp_async16(ks + r * HDP + c, Kg + (size_t)(j0 + r) * HD_ + c);
            else            cp_async16(vs + r * HDP + c, Vg + (size_t)(j0 + r) * HD_ + c);
        }
    };

    const int jstart = (q0 >= WINDOW_) ? (q0 - WINDOW_) : 0;

    // prologue: stage Q (already tf32) + first K/V tile as group 0
    #pragma unroll
    for (int t = 0; t < 8; t++) {
        int idx = tid + t * 256;
        int r = idx >> 5, c = (idx & 31) << 2;
        cp_async16(Qs + r * HDP + c, Qg + (size_t)r * HD_ + c);
    }
    issue_kv(0, jstart);
    CP_COMMIT();

    for (int i = tid; i < QT * HD_; i += 256) {
        int r = i >> 7;
        Os[r * HDP + (i & 127)] = 0.0f;
    }
    if (tid < QT) { m_s[tid] = -1e30f; l_s[tid] = 0.0f; }

    int t_idx = 0;
    for (int j0 = jstart; j0 < q0 + QT; j0 += KT, t_idx++) {
        const int buf = t_idx & 1;
        const int nxt = j0 + KT;
        if (nxt < q0 + QT) issue_kv(buf ^ 1, nxt);
        CP_COMMIT();
        CP_WAIT1();
        __syncthreads();

        const float* Ks = Ks0 + buf * TILE_F;
        const float* Vs = Vs0 + buf * TILE_F;

        // ---- S = Q @ K^T ----
        {
            wmma::fragment<wmma::accumulator, 16, 16, 8, float> sacc[2];
            wmma::fill_fragment(sacc[0], 0.0f);
            wmma::fill_fragment(sacc[1], 0.0f);
            #pragma unroll
            for (int kk = 0; kk < HD_; kk += 8) {
                wmma::fragment<wmma::matrix_a, 16, 16, 8, wmma::precision::tf32, wmma::row_major> af;
                wmma::load_matrix_sync(af, Qs + (wm * 16) * HDP + kk, HDP);
                #pragma unroll
                for (int j = 0; j < 2; j++) {
                    wmma::fragment<wmma::matrix_b, 16, 16, 8, wmma::precision::tf32, wmma::col_major> bf;
                    wmma::load_matrix_sync(bf, Ks + (wn * 32 + j * 16) * HDP + kk, HDP);
                    wmma::mma_sync(sacc[j], af, bf, sacc[j]);
                }
            }
            #pragma unroll
            for (int j = 0; j < 2; j++)
                wmma::store_matrix_sync(Ss + (wm * 16) * STP + wn * 32 + j * 16, sacc[j], STP,
                                        wmma::mem_row_major);
        }
        __syncthreads();

        // ---- masked online softmax: 4 threads per row ----
        {
            const int r  = tid >> 2;
            const int l4 = tid & 3;
            const int gi = q0 + r;
            const float mold = m_s[r];
            float pv[16];
            float mx = -1e30f;
            #pragma unroll
            for (int k = 0; k < 16; k++) {
                int c = l4 + (k << 2);
                int gj = j0 + c;
                float sv = Ss[r * STP + c] * SCALE_F;
                bool ok = (gj <= gi) && ((gi - gj) <= WINDOW_);
                sv = ok ? sv : -1e30f;
                pv[k] = sv;
                mx = fmaxf(mx, sv);
            }
            mx = fmaxf(mx, __shfl_xor_sync(0xffffffffu, mx, 1));
            mx = fmaxf(mx, __shfl_xor_sync(0xffffffffu, mx, 2));
            const float mnew = fmaxf(mold, mx);
            float sum = 0.0f;
            #pragma unroll
            for (int k = 0; k < 16; k++) {
                int c = l4 + (k << 2);
                float p = (pv[k] > -5e29f) ? __expf(pv[k] - mnew) : 0.0f;
                sum += p;
                Ss[r * STP + c] = wmma::__float_to_tf32(p);
            }
            sum += __shfl_xor_sync(0xffffffffu, sum, 1);
            sum += __shfl_xor_sync(0xffffffffu, sum, 2);
            if (l4 == 0) {
                float al = __expf(mold - mnew);
                al_s[r] = al;
                l_s[r]  = l_s[r] * al + sum;
                m_s[r]  = mnew;
            }
        }
        __syncthreads();

        for (int i = tid; i < QT * HD_; i += 256) {
            int r = i >> 7;
            int c = i & 127;
            Os[r * HDP + c] *= al_s[r];
        }
        __syncthreads();

        // ---- O += P @ V ----
        {
            wmma::fragment<wmma::matrix_a, 16, 16, 8, wmma::precision::tf32, wmma::row_major> af[8];
            #pragma unroll
            for (int ki = 0; ki < 8; ki++)
                wmma::load_matrix_sync(af[ki], Ss + (wm * 16) * STP + ki * 8, STP);
            #pragma unroll
            for (int jn = 0; jn < 4; jn++) {
                float* optr = Os + (wm * 16) * HDP + wn * 64 + jn * 16;
                wmma::fragment<wmma::accumulator, 16, 16, 8, float> oc;
                wmma::load_matrix_sync(oc, optr, HDP, wmma::mem_row_major);
                #pragma unroll
                for (int ki = 0; ki < 8; ki++) {
                    wmma::fragment<wmma::matrix_b, 16, 16, 8, wmma::precision::tf32, wmma::row_major> bf;
                    wmma::load_matrix_sync(bf, Vs + (ki * 8) * HDP + wn * 64 + jn * 16, HDP);
                    wmma::mma_sync(oc, af[ki], bf, oc);
                }
                wmma::store_matrix_sync(optr, oc, HDP, wmma::mem_row_major);
            }
        }
        __syncthreads();
    }

    // normalize, round to tf32-RN (feeds wo GEMM via cp.async), write [b, s, h*HD + d]
    for (int i = tid; i < QT * HD_; i += 256) {
        int r = i >> 7;
        int c = i & 127;
        g_attn[((size_t)(b * S_) + q0 + r) * DIM_ + h * HD_ + c] =
            wmma::__float_to_tf32(Os[r * HDP + c] / l_s[r]);
    }
}

// ---------------- launch ----------------
extern "C" void kernel_launch(void* const* d_in, const int* in_sizes, int n_in,
                              void* d_out, int out_size)
{
    (void)in_sizes; (void)n_in; (void)out_size;
    const float* x     = (const float*)d_in[0];
    const float* wq    = (const float*)d_in[1];
    const float* wk    = (const float*)d_in[2];
    const float* wv    = (const float*)d_in[3];
    const float* wo    = (const float*)d_in[4];
    const float* qw    = (const float*)d_in[5];
    const float* kw    = (const float*)d_in[6];
    const float* cosh_ = (const float*)d_in[7];
    const float* sinh_ = (const float*)d_in[8];
    float* out = (float*)d_out;

    float *p_xr, *p_wo_r, *p_w1, *p_xqkv, *p_attn;
    cudaGetSymbolAddress((void**)&p_xr,   g_xr);
    cudaGetSymbolAddress((void**)&p_w1,   g_w1);
    cudaGetSymbolAddress((void**)&p_wo_r, g_wo_r);
    cudaGetSymbolAddress((void**)&p_xqkv, g_xqkv);
    cudaGetSymbolAddress((void**)&p_attn, g_attn);

    cudaFuncSetAttribute(gemm_tf32,   cudaFuncAttributeMaxDynamicSharedMemorySize, GEMM_SMEM);
    cudaFuncSetAttribute(attn_kernel, cudaFuncAttributeMaxDynamicSharedMemorySize, ATT_SMEM_BYTES);

    // tf32-RN pre-rounding (HMMA truncation lossless afterwards)
    {
        int n4x = M_ * DIM_ / 4;
        round_copy<<<(n4x + 255) / 256, 256>>>(p_xr, x, n4x);
        int n4w = DIM_ * QKV_N / 4;
        round_concat_w<<<(n4w + 255) / 256, 256>>>(wq, wk, wv);
        int n4o = DIM_ * DIM_ / 4;
        round_copy<<<(n4o + 255) / 256, 256>>>(p_wo_r, wo, n4o);
    }

    // fused QKV projection: [4096, 7168] = x_r @ concat(wq|wk|wv)
    gemm_tf32<<<dim3(QKV_N / 128, M_ / 128), 256, GEMM_SMEM>>>(p_xr, p_w1, p_xqkv, QKV_N, DIM_);

    // norms + rope + relayout (outputs tf32-RN)
    qnorm_rope_kernel<<<M_, 256>>>(qw, cosh_, sinh_);
    knorm_rope_v_kernel<<<M_, 256>>>(kw, cosh_, sinh_);

    // attention
    attn_kernel<<<dim3(S_ / QT, H_, B_), 256, ATT_SMEM_BYTES>>>();

    // output projection
    gemm_tf32<<<dim3(DIM_ / 128, M_ / 128), 256, GEMM_SMEM>>>(p_attn, p_wo_r, out, DIM_, DIM_);
}

// round 13
// speedup vs baseline: 3.8048x; 3.8048x over previous
#include <cuda_runtime.h>
#include <cuda_fp16.h>
#include <mma.h>
#include <cstdint>

using namespace nvcuda;

// ---------------- problem constants ----------------
#define B_    2
#define S_    2048
#define DIM_  5120
#define H_    40
#define KVH_  8
#define HD_   128
#define NREP_ 5
#define M_    (B_*S_)        // 4096
#define KVDIM_ (KVH_*HD_)    // 1024
#define QKV_N (DIM_ + 2*KVDIM_)   // 7168
#define WINDOW_ 1024
static const float SCALE_F = (float)(1.2079441541679836 / 11.313708498984760390); // mscale / sqrt(128)

// ---------------- scratch (device globals; no allocations allowed) ----------------
__device__ __align__(256) __half g_xh [(size_t)M_*DIM_];       // fp16 x
__device__ __align__(256) __half g_w1 [(size_t)DIM_*QKV_N];    // fp16 concat(wq|wk|wv)
__device__ __align__(256) __half g_wo [(size_t)DIM_*DIM_];     // fp16 wo
__device__ __align__(256) float  g_xqkv[(size_t)M_*QKV_N];     // QKV projection output (fp32)
__device__ __align__(256) __half g_q [(size_t)B_*H_*S_*HD_];   // fp16
__device__ __align__(256) __half g_k [(size_t)B_*KVH_*S_*HD_]; // fp16
__device__ __align__(256) __half g_v [(size_t)B_*KVH_*S_*HD_]; // fp16
__device__ __align__(256) __half g_attn[(size_t)M_*DIM_];      // fp16 attention out

__device__ __forceinline__ void cp_async16(void* dst_smem, const void* src_gmem)
{
    uint32_t d = (uint32_t)__cvta_generic_to_shared(dst_smem);
    asm volatile("cp.async.cg.shared.global [%0], [%1], 16;" :: "r"(d), "l"(src_gmem) : "memory");
}
#define CP_COMMIT() asm volatile("cp.async.commit_group;" ::: "memory")
#define CP_WAIT1()  asm volatile("cp.async.wait_group 1;" ::: "memory")

// ================= fp16 WMMA GEMM, 3-stage cp.async pipeline, BK=32 =================
// C[M,N] = A[M,K] @ B[K,N]; A,B fp16 row-major, C fp32. fp32 accumulate.
// CTA tile 128x128, BK=32, 3 stages -> 18,944 B/stage, 56,832 B total => 2 CTAs/SM.
#define BKH  32
#define LDA  40          // A leading dim (halves); 80 B/row
#define LDB  136         // B leading dim (halves); 272 B/row
#define A_STG_H (128*LDA)            // 5120 halves
#define B_STG_H (BKH*LDB)            // 4352 halves
#define STG_H   (A_STG_H + B_STG_H)  // 9472 halves
#define NSTAGE  3
#define GEMM_SMEM (NSTAGE*STG_H*2)   // 56,832 B

__global__ __launch_bounds__(256, 2) void gemm_f16(const __half* __restrict__ A,
                                                   const __half* __restrict__ Bm,
                                                   float* __restrict__ C,
                                                   int N, int K)
{
    extern __shared__ __half smem_h[];
    const int tid = threadIdx.x;
    const int w   = tid >> 5;
    const int wm  = w & 3;      // 0..3 -> 32-row slab
    const int wn  = w >> 2;     // 0..1 -> 64-col slab
    const int bm0 = blockIdx.y * 128;
    const int bn0 = blockIdx.x * 128;
    const int NK  = K >> 5;     // K/32 steps

    wmma::fragment<wmma::accumulator, 16, 16, 16, float> acc[2][4];
    #pragma unroll
    for (int i = 0; i < 2; i++)
        #pragma unroll
        for (int j = 0; j < 4; j++)
            wmma::fill_fragment(acc[i][j], 0.0f);

    // stage loader: 1024 x 16B chunks (A: 512, B: 512), 4 per thread
    auto issue_stage = [&](int s, int k0) {
        __half* as = smem_h + s * STG_H;
        __half* bs = as + A_STG_H;
        #pragma unroll
        for (int t = 0; t < 4; t++) {
            int idx = tid + t * 256;
            if (idx < 512) {                       // A: 128 rows x 4 chunks (8 halves)
                int m = idx >> 2, c = (idx & 3) << 3;
                cp_async16(as + m * LDA + c, A + (size_t)(bm0 + m) * K + k0 + c);
            } else {                               // B: 32 k-rows x 16 chunks
                int j = idx - 512;
                int kr = j >> 4, c = (j & 15) << 3;
                cp_async16(bs + kr * LDB + c, Bm + (size_t)(k0 + kr) * N + bn0 + c);
            }
        }
    };

    issue_stage(0, 0);
    CP_COMMIT();
    issue_stage(1, BKH);
    CP_COMMIT();

    for (int i = 0; i < NK; i++) {
        CP_WAIT1();
        __syncthreads();

        const __half* as = smem_h + (i % NSTAGE) * STG_H;
        const __half* bs = as + A_STG_H;
        #pragma unroll
        for (int kk = 0; kk < BKH; kk += 16) {
            wmma::fragment<wmma::matrix_a, 16, 16, 16, __half, wmma::row_major> af[2];
            wmma::fragment<wmma::matrix_b, 16, 16, 16, __half, wmma::row_major> bf[4];
            #pragma unroll
            for (int x = 0; x < 2; x++)
                wmma::load_matrix_sync(af[x], as + (wm * 32 + x * 16) * LDA + kk, LDA);
            #pragma unroll
            for (int j = 0; j < 4; j++)
                wmma::load_matrix_sync(bf[j], bs + kk * LDB + wn * 64 + j * 16, LDB);
            #pragma unroll
            for (int x = 0; x < 2; x++)
                #pragma unroll
                for (int j = 0; j < 4; j++)
                    wmma::mma_sync(acc[x][j], af[x], bf[j], acc[x][j]);
        }

        const int nx = i + 2;
        if (nx < NK) issue_stage(nx % NSTAGE, nx * BKH);
        CP_COMMIT();
    }

    #pragma unroll
    for (int x = 0; x < 2; x++)
        #pragma unroll
        for (int j = 0; j < 4; j++)
            wmma::store_matrix_sync(C + (size_t)(bm0 + wm * 32 + x * 16) * N + bn0 + wn * 64 + j * 16,
                                    acc[x][j], N, wmma::mem_row_major);
}

// ================= fp32 -> fp16 conversion passes =================
__global__ __launch_bounds__(256) void conv_half(__half* __restrict__ dst,
                                                 const float* __restrict__ src, int n4)
{
    int i = blockIdx.x * 256 + threadIdx.x;
    if (i >= n4) return;
    float4 v = ((const float4*)src)[i];
    __half2* d = (__half2*)(dst + (size_t)i * 4);
    d[0] = __floats2half2_rn(v.x, v.y);
    d[1] = __floats2half2_rn(v.z, v.w);
}

__global__ __launch_bounds__(256) void conv_concat_w(const float* __restrict__ wq,
                                                     const float* __restrict__ wk,
                                                     const float* __restrict__ wv)
{
    int i = blockIdx.x * 256 + threadIdx.x;        // float4 index into [5120, 7168]
    const int n4 = DIM_ * QKV_N / 4;
    if (i >= n4) return;
    int c = (i % (QKV_N / 4)) * 4;
    int d = i / (QKV_N / 4);
    const float* src;
    if (c < DIM_)                 src = wq + (size_t)d * DIM_   + c;
    else if (c < DIM_ + KVDIM_)   src = wk + (size_t)d * KVDIM_ + (c - DIM_);
    else                          src = wv + (size_t)d * KVDIM_ + (c - DIM_ - KVDIM_);
    float4 v = *(const float4*)src;
    __half2* dp = (__half2*)(g_w1 + (size_t)i * 4);
    dp[0] = __floats2half2_rn(v.x, v.y);
    dp[1] = __floats2half2_rn(v.z, v.w);
}

// ---------------- block sum helper ----------------
__device__ __forceinline__ float block_sum_256(float v, float* red8)
{
    #pragma unroll
    for (int o = 16; o > 0; o >>= 1) v += __shfl_xor_sync(0xffffffffu, v, o);
    if ((threadIdx.x & 31) == 0) red8[threadIdx.x >> 5] = v;
    __syncthreads();
    float total = 0.0f;
    #pragma unroll
    for (int i = 0; i < 8; i++) total += red8[i];
    return total;
}

// ---------------- RMSNorm(5120) + RoPE on Q, re-layout to [b,h,s,d], fp16 out ----------------
__global__ __launch_bounds__(256) void qnorm_rope_kernel(const float* __restrict__ qw,
                                                         const float* __restrict__ cos_h,
                                                         const float* __restrict__ sin_h)
{
    __shared__ float red8[8];
    const int row = blockIdx.x;
    const int b = row >> 11;
    const int s = row & (S_ - 1);
    const float* xr = g_xqkv + (size_t)row * QKV_N;

    float ss = 0.0f;
    for (int i = threadIdx.x; i < DIM_; i += 256) { float v = xr[i]; ss += v * v; }
    float total = block_sum_256(ss, red8);
    const float rms = rsqrtf(total / (float)DIM_ + 1e-6f);

    for (int idx = threadIdx.x; idx < H_ * 64; idx += 256) {
        int h = idx >> 6;
        int d = idx & 63;
        float x1 = xr[h * HD_ + d]      * rms * qw[h * HD_ + d];
        float x2 = xr[h * HD_ + d + 64] * rms * qw[h * HD_ + d + 64];
        float c  = cos_h[s * 64 + d];
        float sn = sin_h[s * 64 + d];
        __half* o = g_q + ((size_t)(b * H_ + h) * S_ + s) * HD_;
        o[d]      = __float2half_rn(x1 * c - x2 * sn);
        o[d + 64] = __float2half_rn(x2 * c + x1 * sn);
    }
}

// ---------------- RMSNorm(1024) + RoPE on K, copy/relayout V, fp16 out ----------------
__global__ __launch_bounds__(256) void knorm_rope_v_kernel(const float* __restrict__ kw,
                                                           const float* __restrict__ cos_h,
                                                           const float* __restrict__ sin_h)
{
    __shared__ float red8[8];
    const int row = blockIdx.x;
    const int b = row >> 11;
    const int s = row & (S_ - 1);
    const float* xk = g_xqkv + (size_t)row * QKV_N + DIM_;
    const float* xv = g_xqkv + (size_t)row * QKV_N + DIM_ + KVDIM_;

    float ss = 0.0f;
    for (int i = threadIdx.x; i < KVDIM_; i += 256) { float v = xk[i]; ss += v * v; }
    float total = block_sum_256(ss, red8);
    const float rms = rsqrtf(total / (float)KVDIM_ + 1e-6f);

    for (int idx = threadIdx.x; idx < KVH_ * 64; idx += 256) {
        int h = idx >> 6;
        int d = idx & 63;
        float x1 = xk[h * HD_ + d]      * rms * kw[h * HD_ + d];
        float x2 = xk[h * HD_ + d + 64] * rms * kw[h * HD_ + d + 64];
        float c  = cos_h[s * 64 + d];
        float sn = sin_h[s * 64 + d];
        __half* o = g_k + ((size_t)(b * KVH_ + h) * S_ + s) * HD_;
        o[d]      = __float2half_rn(x1 * c - x2 * sn);
        o[d + 64] = __float2half_rn(x2 * c + x1 * sn);
    }
    for (int idx = threadIdx.x; idx < KVDIM_; idx += 256) {
        int h = idx >> 7;
        int d = idx & 127;
        g_v[((size_t)(b * KVH_ + h) * S_ + s) * HD_ + d] = __float2half_rn(xv[idx]);
    }
}

// ---------------- flash attention: fp16 tiles, cp.async double-buffered K/V ----------------
#define QT 64
#define KT 64
#define LDQH 136                                   // half leading dim for Q/K/V tiles
#define LDO  132                                   // float leading dim for O
#define STPF 72                                    // float leading dim for S
#define STPH 72                                    // half  leading dim for P
#define QTILE_H (QT * LDQH)                        // 8704 halves per tile
// smem layout (bytes):
//   Qs:    64*136*2 = 17408
//   Ks[2]: 2*17408  = 34816
//   Vs[2]: 2*17408  = 34816
//   Os:    64*132*4 = 33792
//   Ss:    64*72*4  = 18432
//   Ps:    64*72*2  =  9216
//   red:   3*64*4   =   768
#define ATT_SMEM_BYTES (17408 + 34816 + 34816 + 33792 + 18432 + 9216 + 768)

__global__ __launch_bounds__(256) void attn_kernel()
{
    extern __shared__ char asm_raw[];
    __half* Qs  = (__half*)asm_raw;
    __half* Ks0 = Qs + QTILE_H;
    __half* Vs0 = Ks0 + 2 * QTILE_H;
    float*  Os  = (float*)(Vs0 + 2 * QTILE_H);
    float*  Ss  = Os + QT * LDO;
    __half* Ps  = (__half*)(Ss + QT * STPF);
    float*  m_s = (float*)(Ps + QT * STPH);
    float*  l_s = m_s + QT;
    float*  al_s = l_s + QT;

    const int q0  = blockIdx.x * QT;
    const int h   = blockIdx.y;
    const int b   = blockIdx.z;
    const int kvh = h / NREP_;
    const int tid = threadIdx.x;
    const int w   = tid >> 5;
    const int wm  = w & 3;
    const int wn  = w >> 2;

    const __half* Qg = g_q + ((size_t)(b * H_ + h) * S_ + q0) * HD_;
    const __half* Kg = g_k + ((size_t)(b * KVH_ + kvh) * S_) * HD_;
    const __half* Vg = g_v + ((size_t)(b * KVH_ + kvh) * S_) * HD_;

    auto issue_kv = [&](int buf, int j0) {
        __half* ks = Ks0 + buf * QTILE_H;
        __half* vs = Vs0 + buf * QTILE_H;
        #pragma unroll
        for (int t = 0; t < 8; t++) {
            int idx = tid + t * 256;               // 2048 chunks: K 1024 + V 1024
            int r = (idx >> 4) & 63, c = (idx & 15) << 3;
            if (idx < 1024) cp_async16(ks + r * LDQH + c, Kg + (size_t)(j0 + r) * HD_ + c);
            else            cp_async16(vs + r * LDQH + c, Vg + (size_t)(j0 + r) * HD_ + c);
        }
    };

    const int jstart = (q0 >= WINDOW_) ? (q0 - WINDOW_) : 0;

    // prologue: stage Q + first K/V tile as group 0
    #pragma unroll
    for (int t = 0; t < 4; t++) {
        int idx = tid + t * 256;                   // 1024 chunks
        int r = idx >> 4, c = (idx & 15) << 3;
        cp_async16(Qs + r * LDQH + c, Qg + (size_t)r * HD_ + c);
    }
    issue_kv(0, jstart);
    CP_COMMIT();

    for (int i = tid; i < QT * HD_; i += 256) {
        int r = i >> 7;
        Os[r * LDO + (i & 127)] = 0.0f;
    }
    if (tid < QT) { m_s[tid] = -1e30f; l_s[tid] = 0.0f; }

    int t_idx = 0;
    for (int j0 = jstart; j0 < q0 + QT; j0 += KT, t_idx++) {
        const int buf = t_idx & 1;
        const int nxt = j0 + KT;
        if (nxt < q0 + QT) issue_kv(buf ^ 1, nxt);
        CP_COMMIT();
        CP_WAIT1();
        __syncthreads();

        const __half* Ks = Ks0 + buf * QTILE_H;
        const __half* Vs = Vs0 + buf * QTILE_H;

        // ---- S = Q @ K^T (fp16 operands, fp32 accum) ----
        {
            wmma::fragment<wmma::accumulator, 16, 16, 16, float> sacc[2];
            wmma::fill_fragment(sacc[0], 0.0f);
            wmma::fill_fragment(sacc[1], 0.0f);
            #pragma unroll
            for (int kk = 0; kk < HD_; kk += 16) {
                wmma::fragment<wmma::matrix_a, 16, 16, 16, __half, wmma::row_major> af;
                wmma::load_matrix_sync(af, Qs + (wm * 16) * LDQH + kk, LDQH);
                #pragma unroll
                for (int j = 0; j < 2; j++) {
                    wmma::fragment<wmma::matrix_b, 16, 16, 16, __half, wmma::col_major> bf;
                    wmma::load_matrix_sync(bf, Ks + (wn * 32 + j * 16) * LDQH + kk, LDQH);
                    wmma::mma_sync(sacc[j], af, bf, sacc[j]);
                }
            }
            #pragma unroll
            for (int j = 0; j < 2; j++)
                wmma::store_matrix_sync(Ss + (wm * 16) * STPF + wn * 32 + j * 16, sacc[j], STPF,
                                        wmma::mem_row_major);
        }
        __syncthreads();

        // ---- masked online softmax: 4 threads per row; P written as fp16 ----
        {
            const int r  = tid >> 2;
            const int l4 = tid & 3;
            const int gi = q0 + r;
            const float mold = m_s[r];
            float pv[16];
            float mx = -1e30f;
            #pragma unroll
            for (int k = 0; k < 16; k++) {
                int c = l4 + (k << 2);
                int gj = j0 + c;
                float sv = Ss[r * STPF + c] * SCALE_F;
                bool ok = (gj <= gi) && ((gi - gj) <= WINDOW_);
                sv = ok ? sv : -1e30f;
                pv[k] = sv;
                mx = fmaxf(mx, sv);
            }
            mx = fmaxf(mx, __shfl_xor_sync(0xffffffffu, mx, 1));
            mx = fmaxf(mx, __shfl_xor_sync(0xffffffffu, mx, 2));
            const float mnew = fmaxf(mold, mx);
            float sum = 0.0f;
            #pragma unroll
            for (int k = 0; k < 16; k++) {
                int c = l4 + (k << 2);
                float p = (pv[k] > -5e29f) ? __expf(pv[k] - mnew) : 0.0f;
                sum += p;
                Ps[r * STPH + c] = __float2half_rn(p);
            }
            sum += __shfl_xor_sync(0xffffffffu, sum, 1);
            sum += __shfl_xor_sync(0xffffffffu, sum, 2);
            if (l4 == 0) {
                float al = __expf(mold - mnew);
                al_s[r] = al;
                l_s[r]  = l_s[r] * al + sum;
                m_s[r]  = mnew;
            }
        }
        __syncthreads();

        for (int i = tid; i < QT * HD_; i += 256) {
            int r = i >> 7;
            int c = i & 127;
            Os[r * LDO + c] *= al_s[r];
        }
        __syncthreads();

        // ---- O += P @ V (fp16 operands, fp32 accum) ----
        {
            wmma::fragment<wmma::matrix_a, 16, 16, 16, __half, wmma::row_major> af[4];
            #pragma unroll
            for (int ki = 0; ki < 4; ki++)
                wmma::load_matrix_sync(af[ki], Ps + (wm * 16) * STPH + ki * 16, STPH);
            #pragma unroll
            for (int jn = 0; jn < 4; jn++) {
                float* optr = Os + (wm * 16) * LDO + wn * 64 + jn * 16;
                wmma::fragment<wmma::accumulator, 16, 16, 16, float> oc;
                wmma::load_matrix_sync(oc, optr, LDO, wmma::mem_row_major);
                #pragma unroll
                for (int ki = 0; ki < 4; ki++) {
                    wmma::fragment<wmma::matrix_b, 16, 16, 16, __half, wmma::row_major> bf;
                    wmma::load_matrix_sync(bf, Vs + (ki * 16) * LDQH + wn * 64 + jn * 16, LDQH);
                    wmma::mma_sync(oc, af[ki], bf, oc);
                }
                wmma::store_matrix_sync(optr, oc, LDO, wmma::mem_row_major);
            }
        }
        __syncthreads();
    }

    // normalize, convert to fp16 (feeds wo GEMM), write [b, s, h*HD + d]
    for (int i = tid; i < QT * HD_; i += 256) {
        int r = i >> 7;
        int c = i & 127;
        g_attn[((size_t)(b * S_) + q0 + r) * DIM_ + h * HD_ + c] =
            __float2half_rn(Os[r * LDO + c] / l_s[r]);
    }
}

// ---------------- launch ----------------
extern "C" void kernel_launch(void* const* d_in, const int* in_sizes, int n_in,
                              void* d_out, int out_size)
{
    (void)in_sizes; (void)n_in; (void)out_size;
    const float* x     = (const float*)d_in[0];
    const float* wq    = (const float*)d_in[1];
    const float* wk    = (const float*)d_in[2];
    const float* wv    = (const float*)d_in[3];
    const float* wo    = (const float*)d_in[4];
    const float* qw    = (const float*)d_in[5];
    const float* kw    = (const float*)d_in[6];
    const float* cosh_ = (const float*)d_in[7];
    const float* sinh_ = (const float*)d_in[8];
    float* out = (float*)d_out;

    __half *p_xh, *p_w1, *p_wo, *p_attn;
    float  *p_xqkv;
    cudaGetSymbolAddress((void**)&p_xh,   g_xh);
    cudaGetSymbolAddress((void**)&p_w1,   g_w1);
    cudaGetSymbolAddress((void**)&p_wo,   g_wo);
    cudaGetSymbolAddress((void**)&p_xqkv, g_xqkv);
    cudaGetSymbolAddress((void**)&p_attn, g_attn);

    cudaFuncSetAttribute(gemm_f16,    cudaFuncAttributeMaxDynamicSharedMemorySize, GEMM_SMEM);
    cudaFuncSetAttribute(attn_kernel, cudaFuncAttributeMaxDynamicSharedMemorySize, ATT_SMEM_BYTES);

    // fp32 -> fp16 RN conversions
    {
        int n4x = M_ * DIM_ / 4;
        conv_half<<<(n4x + 255) / 256, 256>>>(p_xh, x, n4x);
        int n4w = DIM_ * QKV_N / 4;
        conv_concat_w<<<(n4w + 255) / 256, 256>>>(wq, wk, wv);
        int n4o = DIM_ * DIM_ / 4;
        conv_half<<<(n4o + 255) / 256, 256>>>(p_wo, wo, n4o);
    }

    // fused QKV projection: [4096, 7168] = x_h @ concat(wq|wk|wv)
    gemm_f16<<<dim3(QKV_N / 128, M_ / 128), 256, GEMM_SMEM>>>(p_xh, p_w1, p_xqkv, QKV_N, DIM_);

    // norms + rope + relayout (outputs fp16)
    qnorm_rope_kernel<<<M_, 256>>>(qw, cosh_, sinh_);
    knorm_rope_v_kernel<<<M_, 256>>>(kw, cosh_, sinh_);

    // attention
    attn_kernel<<<dim3(S_ / QT, H_, B_), 256, ATT_SMEM_BYTES>>>();

    // output projection
    gemm_f16<<<dim3(DIM_ / 128, M_ / 128), 256, GEMM_SMEM>>>(p_attn, p_wo, out, DIM_, DIM_);
}

// round 15
// speedup vs baseline: 3.9608x; 1.0410x over previous
#include <cuda_runtime.h>
#include <cuda_fp16.h>
#include <mma.h>
#include <cstdint>

using namespace nvcuda;

// ---------------- problem constants ----------------
#define B_    2
#define S_    2048
#define DIM_  5120
#define H_    40
#define KVH_  8
#define HD_   128
#define NREP_ 5
#define M_    (B_*S_)        // 4096
#define KVDIM_ (KVH_*HD_)    // 1024
#define QKV_N (DIM_ + 2*KVDIM_)   // 7168
#define WINDOW_ 1024
static const float SCALE_F = (float)(1.2079441541679836 / 11.313708498984760390); // mscale / sqrt(128)

// ---------------- scratch (device globals; no allocations allowed) ----------------
__device__ __align__(256) __half g_xh [(size_t)M_*DIM_];       // fp16 x
__device__ __align__(256) __half g_w1 [(size_t)DIM_*QKV_N];    // fp16 concat(wq|wk|wv)
__device__ __align__(256) __half g_wo [(size_t)DIM_*DIM_];     // fp16 wo
__device__ __align__(256) float  g_xqkv[(size_t)M_*QKV_N];     // QKV projection output (fp32)
__device__ __align__(256) __half g_q [(size_t)B_*H_*S_*HD_];   // fp16
__device__ __align__(256) __half g_k [(size_t)B_*KVH_*S_*HD_]; // fp16
__device__ __align__(256) __half g_v [(size_t)B_*KVH_*S_*HD_]; // fp16
__device__ __align__(256) __half g_attn[(size_t)M_*DIM_];      // fp16 attention out

__device__ __forceinline__ void cp_async16(void* dst_smem, const void* src_gmem)
{
    uint32_t d = (uint32_t)__cvta_generic_to_shared(dst_smem);
    asm volatile("cp.async.cg.shared.global [%0], [%1], 16;" :: "r"(d), "l"(src_gmem) : "memory");
}
#define CP_COMMIT() asm volatile("cp.async.commit_group;" ::: "memory")
#define CP_WAIT0()  asm volatile("cp.async.wait_group 0;" ::: "memory")
#define CP_WAIT1()  asm volatile("cp.async.wait_group 1;" ::: "memory")

// ================= fp16 WMMA GEMM, 3-stage cp.async pipeline, BK=64 =================
// C[M,N] = A[M,K] @ B[K,N]; A,B fp16 row-major, C fp32. fp32 accumulate.
// CTA tile 128x128, BK=64, 3 stages -> 35,840 B/stage, 107,520 B total => 2 CTAs/SM.
#define BKH  64
#define LDA  72          // A leading dim (halves); 144 B/row
#define LDB  136         // B leading dim (halves); 272 B/row
#define A_STG_H (128*LDA)            // 9216 halves
#define B_STG_H (BKH*LDB)            // 8704 halves
#define STG_H   (A_STG_H + B_STG_H)  // 17920 halves
#define NSTAGE  3
#define GEMM_SMEM (NSTAGE*STG_H*2)   // 107,520 B

__global__ __launch_bounds__(256, 2) void gemm_f16(const __half* __restrict__ A,
                                                   const __half* __restrict__ Bm,
                                                   float* __restrict__ C,
                                                   int N, int K)
{
    extern __shared__ __half smem_h[];
    const int tid = threadIdx.x;
    const int w   = tid >> 5;
    const int wm  = w & 3;      // 0..3 -> 32-row slab
    const int wn  = w >> 2;     // 0..1 -> 64-col slab
    const int bm0 = blockIdx.y * 128;
    const int bn0 = blockIdx.x * 128;
    const int NK  = K >> 6;     // K/64 steps

    wmma::fragment<wmma::accumulator, 16, 16, 16, float> acc[2][4];
    #pragma unroll
    for (int i = 0; i < 2; i++)
        #pragma unroll
        for (int j = 0; j < 4; j++)
            wmma::fill_fragment(acc[i][j], 0.0f);

    // stage loader: 2048 x 16B chunks (A: 1024, B: 1024), 8 per thread
    auto issue_stage = [&](int s, int k0) {
        __half* as = smem_h + s * STG_H;
        __half* bs = as + A_STG_H;
        #pragma unroll
        for (int t = 0; t < 8; t++) {
            int idx = tid + t * 256;
            if (idx < 1024) {                      // A: 128 rows x 8 chunks (8 halves)
                int m = idx >> 3, c = (idx & 7) << 3;
                cp_async16(as + m * LDA + c, A + (size_t)(bm0 + m) * K + k0 + c);
            } else {                               // B: 64 k-rows x 16 chunks
                int j = idx - 1024;
                int kr = j >> 4, c = (j & 15) << 3;
                cp_async16(bs + kr * LDB + c, Bm + (size_t)(k0 + kr) * N + bn0 + c);
            }
        }
    };

    issue_stage(0, 0);
    CP_COMMIT();
    issue_stage(1, BKH);
    CP_COMMIT();

    for (int i = 0; i < NK; i++) {
        CP_WAIT1();
        __syncthreads();

        const __half* as = smem_h + (i % NSTAGE) * STG_H;
        const __half* bs = as + A_STG_H;
        #pragma unroll
        for (int kk = 0; kk < BKH; kk += 16) {
            wmma::fragment<wmma::matrix_a, 16, 16, 16, __half, wmma::row_major> af[2];
            wmma::fragment<wmma::matrix_b, 16, 16, 16, __half, wmma::row_major> bf[4];
            #pragma unroll
            for (int x = 0; x < 2; x++)
                wmma::load_matrix_sync(af[x], as + (wm * 32 + x * 16) * LDA + kk, LDA);
            #pragma unroll
            for (int j = 0; j < 4; j++)
                wmma::load_matrix_sync(bf[j], bs + kk * LDB + wn * 64 + j * 16, LDB);
            #pragma unroll
            for (int x = 0; x < 2; x++)
                #pragma unroll
                for (int j = 0; j < 4; j++)
                    wmma::mma_sync(acc[x][j], af[x], bf[j], acc[x][j]);
        }

        const int nx = i + 2;
        if (nx < NK) issue_stage(nx % NSTAGE, nx * BKH);
        CP_COMMIT();
    }

    #pragma unroll
    for (int x = 0; x < 2; x++)
        #pragma unroll
        for (int j = 0; j < 4; j++)
            wmma::store_matrix_sync(C + (size_t)(bm0 + wm * 32 + x * 16) * N + bn0 + wn * 64 + j * 16,
                                    acc[x][j], N, wmma::mem_row_major);
}

// ================= fp32 -> fp16 conversion passes =================
__global__ __launch_bounds__(256) void conv_half(__half* __restrict__ dst,
                                                 const float* __restrict__ src, int n4)
{
    int i = blockIdx.x * 256 + threadIdx.x;
    if (i >= n4) return;
    float4 v = ((const float4*)src)[i];
    __half2* d = (__half2*)(dst + (size_t)i * 4);
    d[0] = __floats2half2_rn(v.x, v.y);
    d[1] = __floats2half2_rn(v.z, v.w);
}

__global__ __launch_bounds__(256) void conv_concat_w(const float* __restrict__ wq,
                                                     const float* __restrict__ wk,
                                                     const float* __restrict__ wv)
{
    int i = blockIdx.x * 256 + threadIdx.x;        // float4 index into [5120, 7168]
    const int n4 = DIM_ * QKV_N / 4;
    if (i >= n4) return;
    int c = (i % (QKV_N / 4)) * 4;
    int d = i / (QKV_N / 4);
    const float* src;
    if (c < DIM_)                 src = wq + (size_t)d * DIM_   + c;
    else if (c < DIM_ + KVDIM_)   src = wk + (size_t)d * KVDIM_ + (c - DIM_);
    else                          src = wv + (size_t)d * KVDIM_ + (c - DIM_ - KVDIM_);
    float4 v = *(const float4*)src;
    __half2* dp = (__half2*)(g_w1 + (size_t)i * 4);
    dp[0] = __floats2half2_rn(v.x, v.y);
    dp[1] = __floats2half2_rn(v.z, v.w);
}

// ---------------- block sum helper ----------------
__device__ __forceinline__ float block_sum_256(float v, float* red8)
{
    #pragma unroll
    for (int o = 16; o > 0; o >>= 1) v += __shfl_xor_sync(0xffffffffu, v, o);
    if ((threadIdx.x & 31) == 0) red8[threadIdx.x >> 5] = v;
    __syncthreads();
    float total = 0.0f;
    #pragma unroll
    for (int i = 0; i < 8; i++) total += red8[i];
    return total;
}

// ---------------- RMSNorm(5120) + RoPE on Q, re-layout to [b,h,s,d], fp16 out ----------------
__global__ __launch_bounds__(256) void qnorm_rope_kernel(const float* __restrict__ qw,
                                                         const float* __restrict__ cos_h,
                                                         const float* __restrict__ sin_h)
{
    __shared__ float red8[8];
    const int row = blockIdx.x;
    const int b = row >> 11;
    const int s = row & (S_ - 1);
    const float* xr = g_xqkv + (size_t)row * QKV_N;

    float ss = 0.0f;
    for (int i = threadIdx.x; i < DIM_; i += 256) { float v = xr[i]; ss += v * v; }
    float total = block_sum_256(ss, red8);
    const float rms = rsqrtf(total / (float)DIM_ + 1e-6f);

    for (int idx = threadIdx.x; idx < H_ * 64; idx += 256) {
        int h = idx >> 6;
        int d = idx & 63;
        float x1 = xr[h * HD_ + d]      * rms * qw[h * HD_ + d];
        float x2 = xr[h * HD_ + d + 64] * rms * qw[h * HD_ + d + 64];
        float c  = cos_h[s * 64 + d];
        float sn = sin_h[s * 64 + d];
        __half* o = g_q + ((size_t)(b * H_ + h) * S_ + s) * HD_;
        o[d]      = __float2half_rn(x1 * c - x2 * sn);
        o[d + 64] = __float2half_rn(x2 * c + x1 * sn);
    }
}

// ---------------- RMSNorm(1024) + RoPE on K, copy/relayout V, fp16 out ----------------
__global__ __launch_bounds__(256) void knorm_rope_v_kernel(const float* __restrict__ kw,
                                                           const float* __restrict__ cos_h,
                                                           const float* __restrict__ sin_h)
{
    __shared__ float red8[8];
    const int row = blockIdx.x;
    const int b = row >> 11;
    const int s = row & (S_ - 1);
    const float* xk = g_xqkv + (size_t)row * QKV_N + DIM_;
    const float* xv = g_xqkv + (size_t)row * QKV_N + DIM_ + KVDIM_;

    float ss = 0.0f;
    for (int i = threadIdx.x; i < KVDIM_; i += 256) { float v = xk[i]; ss += v * v; }
    float total = block_sum_256(ss, red8);
    const float rms = rsqrtf(total / (float)KVDIM_ + 1e-6f);

    for (int idx = threadIdx.x; idx < KVH_ * 64; idx += 256) {
        int h = idx >> 6;
        int d = idx & 63;
        float x1 = xk[h * HD_ + d]      * rms * kw[h * HD_ + d];
        float x2 = xk[h * HD_ + d + 64] * rms * kw[h * HD_ + d + 64];
        float c  = cos_h[s * 64 + d];
        float sn = sin_h[s * 64 + d];
        __half* o = g_k + ((size_t)(b * KVH_ + h) * S_ + s) * HD_;
        o[d]      = __float2half_rn(x1 * c - x2 * sn);
        o[d + 64] = __float2half_rn(x2 * c + x1 * sn);
    }
    for (int idx = threadIdx.x; idx < KVDIM_; idx += 256) {
        int h = idx >> 7;
        int d = idx & 127;
        g_v[((size_t)(b * KVH_ + h) * S_ + s) * HD_ + d] = __float2half_rn(xv[idx]);
    }
}

// ---------------- flash attention: 2 CTA/SM, Q in registers, K dbl-buffered, P/S aliased ----
#define QT 64
#define KT 64
#define LDQH 136                                   // half leading dim for K/V tiles (and Q staging)
#define LDO  132                                   // float leading dim for O
#define STPF 72                                    // float leading dim for S
#define STPH 80                                    // half leading dim for P (aliased inside Ss)
#define QTILE_H (QT * LDQH)                        // 8704 halves per tile
// smem (bytes): Ks[2] 34816 + Vs 17408 + Os 33792 + Ss 18432 (P aliased) + red 768 = 105,216
#define ATT_SMEM_BYTES (34816 + 17408 + 33792 + 18432 + 768)

__global__ __launch_bounds__(256, 2) void attn_kernel()
{
    extern __shared__ char asm_raw[];
    __half* Ks0 = (__half*)asm_raw;
    __half* Vs  = Ks0 + 2 * QTILE_H;
    float*  Os  = (float*)(Vs + QTILE_H);
    float*  Ss  = Os + QT * LDO;
    __half* Ps  = (__half*)Ss;                     // alias: written only after all S reads
    float*  m_s = Ss + QT * STPF;
    float*  l_s = m_s + QT;
    float*  al_s = l_s + QT;

    const int q0  = blockIdx.x * QT;
    const int h   = blockIdx.y;
    const int b   = blockIdx.z;
    const int kvh = h / NREP_;
    const int tid = threadIdx.x;
    const int w   = tid >> 5;
    const int lane = tid & 31;
    const int wm  = w & 3;
    const int wn  = w >> 2;

    const __half* Qg = g_q + ((size_t)(b * H_ + h) * S_ + q0) * HD_;
    const __half* Kg = g_k + ((size_t)(b * KVH_ + kvh) * S_) * HD_;
    const __half* Vg = g_v + ((size_t)(b * KVH_ + kvh) * S_) * HD_;

    auto issue_k = [&](int buf, int j0) {
        __half* ks = Ks0 + buf * QTILE_H;
        #pragma unroll
        for (int t = 0; t < 4; t++) {
            int idx = tid + t * 256;               // 1024 chunks
            int r = idx >> 4, c = (idx & 15) << 3;
            cp_async16(ks + r * LDQH + c, Kg + (size_t)(j0 + r) * HD_ + c);
        }
    };
    auto issue_v = [&](int j0) {
        #pragma unroll
        for (int t = 0; t < 4; t++) {
            int idx = tid + t * 256;
            int r = idx >> 4, c = (idx & 15) << 3;
            cp_async16(Vs + r * LDQH + c, Vg + (size_t)(j0 + r) * HD_ + c);
        }
    };

    const int jstart = (q0 >= WINDOW_) ? (q0 - WINDOW_) : 0;

    // ---- prologue: stage Q through Vs, capture as persistent a-fragments ----
    #pragma unroll
    for (int t = 0; t < 4; t++) {
        int idx = tid + t * 256;
        int r = idx >> 4, c = (idx & 15) << 3;
        cp_async16(Vs + r * LDQH + c, Qg + (size_t)r * HD_ + c);
    }
    CP_COMMIT();
    CP_WAIT0();
    __syncthreads();

    wmma::fragment<wmma::matrix_a, 16, 16, 16, __half, wmma::row_major> qf[8];
    #pragma unroll
    for (int kk8 = 0; kk8 < 8; kk8++)
        wmma::load_matrix_sync(qf[kk8], Vs + (wm * 16) * LDQH + kk8 * 16, LDQH);
    __syncthreads();                               // Q frags read before Vs is overwritten

    for (int i = tid; i < QT * HD_; i += 256) {
        int r = i >> 7;
        Os[r * LDO + (i & 127)] = 0.0f;
    }
    if (tid < QT) { m_s[tid] = -1e30f; l_s[tid] = 0.0f; }

    issue_k(0, jstart);
    issue_v(jstart);
    CP_COMMIT();

    int t_idx = 0;
    for (int j0 = jstart; j0 < q0 + QT; j0 += KT, t_idx++) {
        const int buf = t_idx & 1;
        const int nxt = j0 + KT;
        if (nxt < q0 + QT) issue_k(buf ^ 1, nxt);
        CP_COMMIT();
        CP_WAIT1();                                // K_t and V_t resident
        __syncthreads();

        const __half* Ks = Ks0 + buf * QTILE_H;

        // ---- S = Q @ K^T (Q from registers) ----
        {
            wmma::fragment<wmma::accumulator, 16, 16, 16, float> sacc[2];
            wmma::fill_fragment(sacc[0], 0.0f);
            wmma::fill_fragment(sacc[1], 0.0f);
            #pragma unroll
            for (int kk8 = 0; kk8 < 8; kk8++) {
                #pragma unroll
                for (int j = 0; j < 2; j++) {
                    wmma::fragment<wmma::matrix_b, 16, 16, 16, __half, wmma::col_major> bf;
                    wmma::load_matrix_sync(bf, Ks + (wn * 32 + j * 16) * LDQH + kk8 * 16, LDQH);
                    wmma::mma_sync(sacc[j], qf[kk8], bf, sacc[j]);
                }
            }
            #pragma unroll
            for (int j = 0; j < 2; j++)
                wmma::store_matrix_sync(Ss + (wm * 16) * STPF + wn * 32 + j * 16, sacc[j], STPF,
                                        wmma::mem_row_major);
        }
        __syncthreads();

        // ---- softmax phase 1: read S, compute p in registers ----
        const int r  = tid >> 2;
        const int l4 = tid & 3;
        float pv[16];
        float al, mnew, sum;
        {
            const int gi = q0 + r;
            const float mold = m_s[r];
            float mx = -1e30f;
            #pragma unroll
            for (int k = 0; k < 16; k++) {
                int c = l4 + (k << 2);
                int gj = j0 + c;
                float sv = Ss[r * STPF + c] * SCALE_F;
                bool ok = (gj <= gi) && ((gi - gj) <= WINDOW_);
                sv = ok ? sv : -1e30f;
                pv[k] = sv;
                mx = fmaxf(mx, sv);
            }
            mx = fmaxf(mx, __shfl_xor_sync(0xffffffffu, mx, 1));
            mx = fmaxf(mx, __shfl_xor_sync(0xffffffffu, mx, 2));
            mnew = fmaxf(mold, mx);
            sum = 0.0f;
            #pragma unroll
            for (int k = 0; k < 16; k++) {
                float p = (pv[k] > -5e29f) ? __expf(pv[k] - mnew) : 0.0f;
                pv[k] = p;
                sum += p;
            }
            sum += __shfl_xor_sync(0xffffffffu, sum, 1);
            sum += __shfl_xor_sync(0xffffffffu, sum, 2);
            al = __expf(mold - mnew);
        }
        __syncthreads();                           // all S reads complete

        // ---- softmax phase 2: write P (half, aliased) + per-row stats ----
        #pragma unroll
        for (int k = 0; k < 16; k++) {
            int c = l4 + (k << 2);
            Ps[r * STPH + c] = __float2half_rn(pv[k]);
        }
        if (l4 == 0) {
            al_s[r] = al;
            l_s[r]  = l_s[r] * al + sum;
            m_s[r]  = mnew;
        }
        __syncthreads();                           // P + al visible

        // ---- warp-local O rescale (own 16x64 slab) ----
        #pragma unroll
        for (int rr = 0; rr < 16; rr++) {
            const float a = al_s[wm * 16 + rr];
            float* orow = Os + (wm * 16 + rr) * LDO + wn * 64;
            for (int cc = lane; cc < 64; cc += 32) orow[cc] *= a;
        }

        // ---- O += P @ V ----
        {
            wmma::fragment<wmma::matrix_a, 16, 16, 16, __half, wmma::row_major> af[4];
            #pragma unroll
            for (int ki = 0; ki < 4; ki++)
                wmma::load_matrix_sync(af[ki], Ps + (wm * 16) * STPH + ki * 16, STPH);
            #pragma unroll
            for (int jn = 0; jn < 4; jn++) {
                float* optr = Os + (wm * 16) * LDO + wn * 64 + jn * 16;
                wmma::fragment<wmma::accumulator, 16, 16, 16, float> oc;
                wmma::load_matrix_sync(oc, optr, LDO, wmma::mem_row_major);
                #pragma unroll
                for (int ki = 0; ki < 4; ki++) {
                    wmma::fragment<wmma::matrix_b, 16, 16, 16, __half, wmma::row_major> bf;
                    wmma::load_matrix_sync(bf, Vs + (ki * 16) * LDQH + wn * 64 + jn * 16, LDQH);
                    wmma::mma_sync(oc, af[ki], bf, oc);
                }
                wmma::store_matrix_sync(optr, oc, LDO, wmma::mem_row_major);
            }
        }
        __syncthreads();                           // all PV reads of Vs complete

        if (nxt < q0 + QT) issue_v(nxt);
        CP_COMMIT();
    }

    // normalize, convert to fp16 (feeds wo GEMM), write [b, s, h*HD + d]
    for (int i = tid; i < QT * HD_; i += 256) {
        int r = i >> 7;
        int c = i & 127;
        g_attn[((size_t)(b * S_) + q0 + r) * DIM_ + h * HD_ + c] =
            __float2half_rn(Os[r * LDO + c] / l_s[r]);
    }
}

// ---------------- launch ----------------
extern "C" void kernel_launch(void* const* d_in, const int* in_sizes, int n_in,
                              void* d_out, int out_size)
{
    (void)in_sizes; (void)n_in; (void)out_size;
    const float* x     = (const float*)d_in[0];
    const float* wq    = (const float*)d_in[1];
    const float* wk    = (const float*)d_in[2];
    const float* wv    = (const float*)d_in[3];
    const float* wo    = (const float*)d_in[4];
    const float* qw    = (const float*)d_in[5];
    const float* kw    = (const float*)d_in[6];
    const float* cosh_ = (const float*)d_in[7];
    const float* sinh_ = (const float*)d_in[8];
    float* out = (float*)d_out;

    __half *p_xh, *p_w1, *p_wo, *p_attn;
    float  *p_xqkv;
    cudaGetSymbolAddress((void**)&p_xh,   g_xh);
    cudaGetSymbolAddress((void**)&p_w1,   g_w1);
    cudaGetSymbolAddress((void**)&p_wo,   g_wo);
    cudaGetSymbolAddress((void**)&p_xqkv, g_xqkv);
    cudaGetSymbolAddress((void**)&p_attn, g_attn);

    cudaFuncSetAttribute(gemm_f16,    cudaFuncAttributeMaxDynamicSharedMemorySize, GEMM_SMEM);
    cudaFuncSetAttribute(attn_kernel, cudaFuncAttributeMaxDynamicSharedMemorySize, ATT_SMEM_BYTES);

    // fp32 -> fp16 RN conversions
    {
        int n4x = M_ * DIM_ / 4;
        conv_half<<<(n4x + 255) / 256, 256>>>(p_xh, x, n4x);
        int n4w = DIM_ * QKV_N / 4;
        conv_concat_w<<<(n4w + 255) / 256, 256>>>(wq, wk, wv);
        int n4o = DIM_ * DIM_ / 4;
        conv_half<<<(n4o + 255) / 256, 256>>>(p_wo, wo, n4o);
    }

    // fused QKV projection: [4096, 7168] = x_h @ concat(wq|wk|wv)
    gemm_f16<<<dim3(QKV_N / 128, M_ / 128), 256, GEMM_SMEM>>>(p_xh, p_w1, p_xqkv, QKV_N, DIM_);

    // norms + rope + relayout (outputs fp16)
    qnorm_rope_kernel<<<M_, 256>>>(qw, cosh_, sinh_);
    knorm_rope_v_kernel<<<M_, 256>>>(kw, cosh_, sinh_);

    // attention
    attn_kernel<<<dim3(S_ / QT, H_, B_), 256, ATT_SMEM_BYTES>>>();

    // output projection
    gemm_f16<<<dim3(DIM_ / 128, M_ / 128), 256, GEMM_SMEM>>>(p_attn, p_wo, out, DIM_, DIM_);
}

// round 16
// speedup vs baseline: 4.6891x; 1.1839x over previous
#include <cuda_runtime.h>
#include <cuda_fp16.h>
#include <mma.h>
#include <cstdint>

using namespace nvcuda;

// ---------------- problem constants ----------------
#define B_    2
#define S_    2048
#define DIM_  5120
#define H_    40
#define KVH_  8
#define HD_   128
#define NREP_ 5
#define M_    (B_*S_)        // 4096
#define KVDIM_ (KVH_*HD_)    // 1024
#define QKV_N (DIM_ + 2*KVDIM_)   // 7168
#define WINDOW_ 1024
static const float SCALE_F = (float)(1.2079441541679836 / 11.313708498984760390); // mscale / sqrt(128)

// ---------------- scratch (device globals; no allocations allowed) ----------------
__device__ __align__(256) __half g_xh [(size_t)M_*DIM_];       // fp16 x
__device__ __align__(256) __half g_w1 [(size_t)DIM_*QKV_N];    // fp16 concat(wq|wk|wv)
__device__ __align__(256) __half g_wo [(size_t)DIM_*DIM_];     // fp16 wo
__device__ __align__(256) float  g_xqkv[(size_t)M_*QKV_N];     // QKV projection output (fp32)
__device__ __align__(256) __half g_q [(size_t)B_*H_*S_*HD_];   // fp16
__device__ __align__(256) __half g_k [(size_t)B_*KVH_*S_*HD_]; // fp16
__device__ __align__(256) __half g_v [(size_t)B_*KVH_*S_*HD_]; // fp16
__device__ __align__(256) __half g_attn[(size_t)M_*DIM_];      // fp16 attention out

__device__ __forceinline__ void cp_async16(void* dst_smem, const void* src_gmem)
{
    uint32_t d = (uint32_t)__cvta_generic_to_shared(dst_smem);
    asm volatile("cp.async.cg.shared.global [%0], [%1], 16;" :: "r"(d), "l"(src_gmem) : "memory");
}
#define CP_COMMIT() asm volatile("cp.async.commit_group;" ::: "memory")
#define CP_WAIT1()  asm volatile("cp.async.wait_group 1;" ::: "memory")

// ================= fp16 WMMA GEMM (R13 proven config: BK=32, 3-stage) =================
// C[M,N] = A[M,K] @ B[K,N]; A,B fp16 row-major, C fp32. fp32 accumulate.
// CTA tile 128x128, BK=32, 3 stages -> 18,944 B/stage, 56,832 B total => 2 CTAs/SM.
#define BKH  32
#define LDA  40          // A leading dim (halves); 80 B/row
#define LDB  136         // B leading dim (halves); 272 B/row
#define A_STG_H (128*LDA)            // 5120 halves
#define B_STG_H (BKH*LDB)            // 4352 halves
#define STG_H   (A_STG_H + B_STG_H)  // 9472 halves
#define NSTAGE  3
#define GEMM_SMEM (NSTAGE*STG_H*2)   // 56,832 B

__global__ __launch_bounds__(256, 2) void gemm_f16(const __half* __restrict__ A,
                                                   const __half* __restrict__ Bm,
                                                   float* __restrict__ C,
                                                   int N, int K)
{
    extern __shared__ __half smem_h[];
    const int tid = threadIdx.x;
    const int w   = tid >> 5;
    const int wm  = w & 3;
    const int wn  = w >> 2;
    const int bm0 = blockIdx.y * 128;
    const int bn0 = blockIdx.x * 128;
    const int NK  = K >> 5;

    wmma::fragment<wmma::accumulator, 16, 16, 16, float> acc[2][4];
    #pragma unroll
    for (int i = 0; i < 2; i++)
        #pragma unroll
        for (int j = 0; j < 4; j++)
            wmma::fill_fragment(acc[i][j], 0.0f);

    auto issue_stage = [&](int s, int k0) {
        __half* as = smem_h + s * STG_H;
        __half* bs = as + A_STG_H;
        #pragma unroll
        for (int t = 0; t < 4; t++) {
            int idx = tid + t * 256;
            if (idx < 512) {
                int m = idx >> 2, c = (idx & 3) << 3;
                cp_async16(as + m * LDA + c, A + (size_t)(bm0 + m) * K + k0 + c);
            } else {
                int j = idx - 512;
                int kr = j >> 4, c = (j & 15) << 3;
                cp_async16(bs + kr * LDB + c, Bm + (size_t)(k0 + kr) * N + bn0 + c);
            }
        }
    };

    issue_stage(0, 0);
    CP_COMMIT();
    issue_stage(1, BKH);
    CP_COMMIT();

    for (int i = 0; i < NK; i++) {
        CP_WAIT1();
        __syncthreads();

        const __half* as = smem_h + (i % NSTAGE) * STG_H;
        const __half* bs = as + A_STG_H;
        #pragma unroll
        for (int kk = 0; kk < BKH; kk += 16) {
            wmma::fragment<wmma::matrix_a, 16, 16, 16, __half, wmma::row_major> af[2];
            wmma::fragment<wmma::matrix_b, 16, 16, 16, __half, wmma::row_major> bf[4];
            #pragma unroll
            for (int x = 0; x < 2; x++)
                wmma::load_matrix_sync(af[x], as + (wm * 32 + x * 16) * LDA + kk, LDA);
            #pragma unroll
            for (int j = 0; j < 4; j++)
                wmma::load_matrix_sync(bf[j], bs + kk * LDB + wn * 64 + j * 16, LDB);
            #pragma unroll
            for (int x = 0; x < 2; x++)
                #pragma unroll
                for (int j = 0; j < 4; j++)
                    wmma::mma_sync(acc[x][j], af[x], bf[j], acc[x][j]);
        }

        const int nx = i + 2;
        if (nx < NK) issue_stage(nx % NSTAGE, nx * BKH);
        CP_COMMIT();
    }

    #pragma unroll
    for (int x = 0; x < 2; x++)
        #pragma unroll
        for (int j = 0; j < 4; j++)
            wmma::store_matrix_sync(C + (size_t)(bm0 + wm * 32 + x * 16) * N + bn0 + wn * 64 + j * 16,
                                    acc[x][j], N, wmma::mem_row_major);
}

// ================= fp32 -> fp16 conversion passes =================
__global__ __launch_bounds__(256) void conv_half(__half* __restrict__ dst,
                                                 const float* __restrict__ src, int n4)
{
    int i = blockIdx.x * 256 + threadIdx.x;
    if (i >= n4) return;
    float4 v = ((const float4*)src)[i];
    __half2* d = (__half2*)(dst + (size_t)i * 4);
    d[0] = __floats2half2_rn(v.x, v.y);
    d[1] = __floats2half2_rn(v.z, v.w);
}

__global__ __launch_bounds__(256) void conv_concat_w(const float* __restrict__ wq,
                                                     const float* __restrict__ wk,
                                                     const float* __restrict__ wv)
{
    int i = blockIdx.x * 256 + threadIdx.x;
    const int n4 = DIM_ * QKV_N / 4;
    if (i >= n4) return;
    int c = (i % (QKV_N / 4)) * 4;
    int d = i / (QKV_N / 4);
    const float* src;
    if (c < DIM_)                 src = wq + (size_t)d * DIM_   + c;
    else if (c < DIM_ + KVDIM_)   src = wk + (size_t)d * KVDIM_ + (c - DIM_);
    else                          src = wv + (size_t)d * KVDIM_ + (c - DIM_ - KVDIM_);
    float4 v = *(const float4*)src;
    __half2* dp = (__half2*)(g_w1 + (size_t)i * 4);
    dp[0] = __floats2half2_rn(v.x, v.y);
    dp[1] = __floats2half2_rn(v.z, v.w);
}

// ---------------- block sum helper ----------------
__device__ __forceinline__ float block_sum_256(float v, float* red8)
{
    #pragma unroll
    for (int o = 16; o > 0; o >>= 1) v += __shfl_xor_sync(0xffffffffu, v, o);
    if ((threadIdx.x & 31) == 0) red8[threadIdx.x >> 5] = v;
    __syncthreads();
    float total = 0.0f;
    #pragma unroll
    for (int i = 0; i < 8; i++) total += red8[i];
    return total;
}

// ---------------- RMSNorm(5120) + RoPE on Q, re-layout to [b,h,s,d], fp16 out ----------------
__global__ __launch_bounds__(256) void qnorm_rope_kernel(const float* __restrict__ qw,
                                                         const float* __restrict__ cos_h,
                                                         const float* __restrict__ sin_h)
{
    __shared__ float red8[8];
    const int row = blockIdx.x;
    const int b = row >> 11;
    const int s = row & (S_ - 1);
    const float* xr = g_xqkv + (size_t)row * QKV_N;

    float ss = 0.0f;
    for (int i = threadIdx.x; i < DIM_; i += 256) { float v = xr[i]; ss += v * v; }
    float total = block_sum_256(ss, red8);
    const float rms = rsqrtf(total / (float)DIM_ + 1e-6f);

    for (int idx = threadIdx.x; idx < H_ * 64; idx += 256) {
        int h = idx >> 6;
        int d = idx & 63;
        float x1 = xr[h * HD_ + d]      * rms * qw[h * HD_ + d];
        float x2 = xr[h * HD_ + d + 64] * rms * qw[h * HD_ + d + 64];
        float c  = cos_h[s * 64 + d];
        float sn = sin_h[s * 64 + d];
        __half* o = g_q + ((size_t)(b * H_ + h) * S_ + s) * HD_;
        o[d]      = __float2half_rn(x1 * c - x2 * sn);
        o[d + 64] = __float2half_rn(x2 * c + x1 * sn);
    }
}

// ---------------- RMSNorm(1024) + RoPE on K, copy/relayout V, fp16 out ----------------
__global__ __launch_bounds__(256) void knorm_rope_v_kernel(const float* __restrict__ kw,
                                                           const float* __restrict__ cos_h,
                                                           const float* __restrict__ sin_h)
{
    __shared__ float red8[8];
    const int row = blockIdx.x;
    const int b = row >> 11;
    const int s = row & (S_ - 1);
    const float* xk = g_xqkv + (size_t)row * QKV_N + DIM_;
    const float* xv = g_xqkv + (size_t)row * QKV_N + DIM_ + KVDIM_;

    float ss = 0.0f;
    for (int i = threadIdx.x; i < KVDIM_; i += 256) { float v = xk[i]; ss += v * v; }
    float total = block_sum_256(ss, red8);
    const float rms = rsqrtf(total / (float)KVDIM_ + 1e-6f);

    for (int idx = threadIdx.x; idx < KVH_ * 64; idx += 256) {
        int h = idx >> 6;
        int d = idx & 63;
        float x1 = xk[h * HD_ + d]      * rms * kw[h * HD_ + d];
        float x2 = xk[h * HD_ + d + 64] * rms * kw[h * HD_ + d + 64];
        float c  = cos_h[s * 64 + d];
        float sn = sin_h[s * 64 + d];
        __half* o = g_k + ((size_t)(b * KVH_ + h) * S_ + s) * HD_;
        o[d]      = __float2half_rn(x1 * c - x2 * sn);
        o[d + 64] = __float2half_rn(x2 * c + x1 * sn);
    }
    for (int idx = threadIdx.x; idx < KVDIM_; idx += 256) {
        int h = idx >> 7;
        int d = idx & 127;
        g_v[((size_t)(b * KVH_ + h) * S_ + s) * HD_ + d] = __float2half_rn(xv[idx]);
    }
}

// ============ flash attention: raw mma.sync, register-resident S/P/O, QT=128 ============
#define QT2   128
#define KT2   64
#define ALD   136                                  // K/V tile leading dim (halves)
#define KVTILE_H (KT2 * ALD)                       // 8704 halves
#define ATT_SMEM_BYTES (4 * KVTILE_H * 2)          // 69,632 B (K dbl + V dbl)

__device__ __forceinline__ void ldsm_x4(uint32_t& r0, uint32_t& r1, uint32_t& r2, uint32_t& r3,
                                        uint32_t addr)
{
    asm volatile("ldmatrix.sync.aligned.m8n8.x4.shared.b16 {%0,%1,%2,%3}, [%4];"
                 : "=r"(r0), "=r"(r1), "=r"(r2), "=r"(r3) : "r"(addr));
}
__device__ __forceinline__ void ldsm_x4_t(uint32_t& r0, uint32_t& r1, uint32_t& r2, uint32_t& r3,
                                          uint32_t addr)
{
    asm volatile("ldmatrix.sync.aligned.m8n8.x4.trans.shared.b16 {%0,%1,%2,%3}, [%4];"
                 : "=r"(r0), "=r"(r1), "=r"(r2), "=r"(r3) : "r"(addr));
}
__device__ __forceinline__ void mma16816(float* c, uint32_t a0, uint32_t a1, uint32_t a2, uint32_t a3,
                                         uint32_t b0, uint32_t b1)
{
    asm volatile("mma.sync.aligned.m16n8k16.row.col.f32.f16.f16.f32 "
                 "{%0,%1,%2,%3}, {%4,%5,%6,%7}, {%8,%9}, {%0,%1,%2,%3};"
                 : "+f"(c[0]), "+f"(c[1]), "+f"(c[2]), "+f"(c[3])
                 : "r"(a0), "r"(a1), "r"(a2), "r"(a3), "r"(b0), "r"(b1));
}
__device__ __forceinline__ uint32_t f2h2(float a, float b)
{
    __half2 h = __floats2half2_rn(a, b);
    return *reinterpret_cast<uint32_t*>(&h);
}

__global__ __launch_bounds__(256, 1) void attn_kernel()
{
    extern __shared__ __half smemh[];
    __half* Ks0 = smemh;                           // 2 x 64x136
    __half* Vs0 = Ks0 + 2 * KVTILE_H;              // 2 x 64x136

    const int q0   = blockIdx.x * QT2;
    const int h    = blockIdx.y;
    const int b    = blockIdx.z;
    const int kvh  = h / NREP_;
    const int tid  = threadIdx.x;
    const int w    = tid >> 5;
    const int lane = tid & 31;
    const int gid  = lane >> 2;                    // group (row within 8)
    const int qd   = lane & 3;                     // quad thread (col pair)

    const __half* Qg = g_q + ((size_t)(b * H_ + h) * S_ + q0) * HD_;
    const __half* Kg = g_k + ((size_t)(b * KVH_ + kvh) * S_) * HD_;
    const __half* Vg = g_v + ((size_t)(b * KVH_ + kvh) * S_) * HD_;

    auto issue_kv = [&](int buf, int j0) {
        __half* ks = Ks0 + buf * KVTILE_H;
        __half* vs = Vs0 + buf * KVTILE_H;
        #pragma unroll
        for (int t = 0; t < 8; t++) {
            int idx = tid + t * 256;               // 2048 chunks: K 1024 + V 1024
            int r = (idx >> 4) & 63, c = (idx & 15) << 3;
            if (idx < 1024) cp_async16(ks + r * ALD + c, Kg + (size_t)(j0 + r) * HD_ + c);
            else            cp_async16(vs + r * ALD + c, Vg + (size_t)(j0 + r) * HD_ + c);
        }
    };

    // ---- persistent Q a-fragments (documented m16n8k16 A layout), direct from gmem ----
    uint32_t qa[8][4];
    {
        const __half* r0p = Qg + (size_t)(w * 16 + gid) * HD_ + qd * 2;
        const __half* r1p = r0p + 8 * HD_;
        #pragma unroll
        for (int kt = 0; kt < 8; kt++) {
            qa[kt][0] = *(const uint32_t*)(r0p + kt * 16);
            qa[kt][1] = *(const uint32_t*)(r1p + kt * 16);
            qa[kt][2] = *(const uint32_t*)(r0p + kt * 16 + 8);
            qa[kt][3] = *(const uint32_t*)(r1p + kt * 16 + 8);
        }
    }

    float o[16][4];
    #pragma unroll
    for (int jt = 0; jt < 16; jt++)
        #pragma unroll
        for (int e = 0; e < 4; e++) o[jt][e] = 0.0f;
    float rm0 = -1e30f, rm1 = -1e30f, rl0 = 0.0f, rl1 = 0.0f;

    const int jstart = (q0 >= WINDOW_) ? (q0 - WINDOW_) : 0;
    issue_kv(0, jstart);
    CP_COMMIT();
    if (jstart + KT2 < q0 + QT2) issue_kv(1, jstart + KT2);
    CP_COMMIT();

    const uint32_t ks_u0 = (uint32_t)__cvta_generic_to_shared(Ks0);
    const uint32_t vs_u0 = (uint32_t)__cvta_generic_to_shared(Vs0);
    const uint32_t laddrQK = (uint32_t)((((lane >> 4) & 1) * 8 + (lane & 7)) * (ALD * 2)
                                        + ((lane >> 3) & 1) * 16);
    const uint32_t laddrPV = (uint32_t)((((lane >> 3) & 1) * 8 + (lane & 7)) * (ALD * 2)
                                        + ((lane >> 4) & 1) * 16);
    const int gi0 = q0 + w * 16 + gid;
    const int gi1 = gi0 + 8;

    int t_idx = 0;
    for (int j0 = jstart; j0 < q0 + QT2; j0 += KT2, t_idx++) {
        const int buf = t_idx & 1;
        CP_WAIT1();
        __syncthreads();                           // tile t resident; all warps synced

        const uint32_t ksb = ks_u0 + (uint32_t)(buf * KVTILE_H * 2) + laddrQK;
        const uint32_t vsb = vs_u0 + (uint32_t)(buf * KVTILE_H * 2) + laddrPV;

        // ---- S = Q @ K^T : 8 n8-tiles in registers ----
        float sacc[8][4];
        #pragma unroll
        for (int nt = 0; nt < 8; nt++)
            #pragma unroll
            for (int e = 0; e < 4; e++) sacc[nt][e] = 0.0f;

        #pragma unroll
        for (int kt = 0; kt < 8; kt++) {
            #pragma unroll
            for (int ntp = 0; ntp < 4; ntp++) {
                uint32_t b0, b1, b2, b3;
                ldsm_x4(b0, b1, b2, b3, ksb + (uint32_t)(ntp * (16 * ALD * 2) + kt * 32));
                mma16816(sacc[2 * ntp],     qa[kt][0], qa[kt][1], qa[kt][2], qa[kt][3], b0, b1);
                mma16816(sacc[2 * ntp + 1], qa[kt][0], qa[kt][1], qa[kt][2], qa[kt][3], b2, b3);
            }
        }

        // ---- online softmax, fully in registers (quad shares rows) ----
        float mx0 = -1e30f, mx1 = -1e30f;
        #pragma unroll
        for (int nt = 0; nt < 8; nt++) {
            int gj = j0 + nt * 8 + qd * 2;
            #pragma unroll
            for (int e = 0; e < 2; e++) {
                int gjj = gj + e;
                bool ok0 = (gjj <= gi0) && (gi0 - gjj <= WINDOW_);
                bool ok1 = (gjj <= gi1) && (gi1 - gjj <= WINDOW_);
                float v0 = ok0 ? sacc[nt][e]     * SCALE_F : -1e30f;
                float v1 = ok1 ? sacc[nt][2 + e] * SCALE_F : -1e30f;
                sacc[nt][e] = v0; sacc[nt][2 + e] = v1;
                mx0 = fmaxf(mx0, v0); mx1 = fmaxf(mx1, v1);
            }
        }
        mx0 = fmaxf(mx0, __shfl_xor_sync(0xffffffffu, mx0, 1));
        mx0 = fmaxf(mx0, __shfl_xor_sync(0xffffffffu, mx0, 2));
        mx1 = fmaxf(mx1, __shfl_xor_sync(0xffffffffu, mx1, 1));
        mx1 = fmaxf(mx1, __shfl_xor_sync(0xffffffffu, mx1, 2));
        const float mn0 = fmaxf(rm0, mx0), mn1 = fmaxf(rm1, mx1);
        const float al0 = __expf(rm0 - mn0), al1 = __expf(rm1 - mn1);
        float s0 = 0.0f, s1 = 0.0f;
        #pragma unroll
        for (int nt = 0; nt < 8; nt++) {
            #pragma unroll
            for (int e = 0; e < 2; e++) {
                float p0 = (sacc[nt][e]     > -5e29f) ? __expf(sacc[nt][e]     - mn0) : 0.0f;
                float p1 = (sacc[nt][2 + e] > -5e29f) ? __expf(sacc[nt][2 + e] - mn1) : 0.0f;
                sacc[nt][e] = p0; sacc[nt][2 + e] = p1;
                s0 += p0; s1 += p1;
            }
        }
        s0 += __shfl_xor_sync(0xffffffffu, s0, 1);
        s0 += __shfl_xor_sync(0xffffffffu, s0, 2);
        s1 += __shfl_xor_sync(0xffffffffu, s1, 1);
        s1 += __shfl_xor_sync(0xffffffffu, s1, 2);
        rl0 = rl0 * al0 + s0; rl1 = rl1 * al1 + s1;
        rm0 = mn0; rm1 = mn1;

        // ---- rescale O (registers) ----
        #pragma unroll
        for (int jt = 0; jt < 16; jt++) {
            o[jt][0] *= al0; o[jt][1] *= al0;
            o[jt][2] *= al1; o[jt][3] *= al1;
        }

        // ---- O += P @ V : P repacked c-frag -> a-frag in registers ----
        #pragma unroll
        for (int kt2 = 0; kt2 < 4; kt2++) {
            uint32_t a0 = f2h2(sacc[2 * kt2][0],     sacc[2 * kt2][1]);
            uint32_t a1 = f2h2(sacc[2 * kt2][2],     sacc[2 * kt2][3]);
            uint32_t a2 = f2h2(sacc[2 * kt2 + 1][0], sacc[2 * kt2 + 1][1]);
            uint32_t a3 = f2h2(sacc[2 * kt2 + 1][2], sacc[2 * kt2 + 1][3]);
            #pragma unroll
            for (int jtp = 0; jtp < 8; jtp++) {
                uint32_t b0, b1, b2, b3;
                ldsm_x4_t(b0, b1, b2, b3, vsb + (uint32_t)(kt2 * (16 * ALD * 2) + jtp * 32));
                mma16816(o[2 * jtp],     a0, a1, a2, a3, b0, b1);
                mma16816(o[2 * jtp + 1], a0, a1, a2, a3, b2, b3);
            }
        }

        __syncthreads();                           // all warps done reading buf
        if (j0 + 2 * KT2 < q0 + QT2) issue_kv(buf, j0 + 2 * KT2);
        CP_COMMIT();
    }

    // ---- epilogue: normalize, write fp16 [b, s, h*HD + d] ----
    const float inv0 = 1.0f / rl0, inv1 = 1.0f / rl1;
    __half* orow0 = g_attn + ((size_t)(b * S_) + q0 + w * 16 + gid) * DIM_ + h * HD_ + qd * 2;
    __half* orow1 = orow0 + (size_t)8 * DIM_;
    #pragma unroll
    for (int jt = 0; jt < 16; jt++) {
        *(uint32_t*)(orow0 + jt * 8) = f2h2(o[jt][0] * inv0, o[jt][1] * inv0);
        *(uint32_t*)(orow1 + jt * 8) = f2h2(o[jt][2] * inv1, o[jt][3] * inv1);
    }
}

// ---------------- launch ----------------
extern "C" void kernel_launch(void* const* d_in, const int* in_sizes, int n_in,
                              void* d_out, int out_size)
{
    (void)in_sizes; (void)n_in; (void)out_size;
    const float* x     = (const float*)d_in[0];
    const float* wq    = (const float*)d_in[1];
    const float* wk    = (const float*)d_in[2];
    const float* wv    = (const float*)d_in[3];
    const float* wo    = (const float*)d_in[4];
    const float* qw    = (const float*)d_in[5];
    const float* kw    = (const float*)d_in[6];
    const float* cosh_ = (const float*)d_in[7];
    const float* sinh_ = (const float*)d_in[8];
    float* out = (float*)d_out;

    __half *p_xh, *p_w1, *p_wo, *p_attn;
    float  *p_xqkv;
    cudaGetSymbolAddress((void**)&p_xh,   g_xh);
    cudaGetSymbolAddress((void**)&p_w1,   g_w1);
    cudaGetSymbolAddress((void**)&p_wo,   g_wo);
    cudaGetSymbolAddress((void**)&p_xqkv, g_xqkv);
    cudaGetSymbolAddress((void**)&p_attn, g_attn);

    cudaFuncSetAttribute(gemm_f16,    cudaFuncAttributeMaxDynamicSharedMemorySize, GEMM_SMEM);
    cudaFuncSetAttribute(attn_kernel, cudaFuncAttributeMaxDynamicSharedMemorySize, ATT_SMEM_BYTES);

    // fp32 -> fp16 RN conversions
    {
        int n4x = M_ * DIM_ / 4;
        conv_half<<<(n4x + 255) / 256, 256>>>(p_xh, x, n4x);
        int n4w = DIM_ * QKV_N / 4;
        conv_concat_w<<<(n4w + 255) / 256, 256>>>(wq, wk, wv);
        int n4o = DIM_ * DIM_ / 4;
        conv_half<<<(n4o + 255) / 256, 256>>>(p_wo, wo, n4o);
    }

    // fused QKV projection: [4096, 7168] = x_h @ concat(wq|wk|wv)
    gemm_f16<<<dim3(QKV_N / 128, M_ / 128), 256, GEMM_SMEM>>>(p_xh, p_w1, p_xqkv, QKV_N, DIM_);

    // norms + rope + relayout (outputs fp16)
    qnorm_rope_kernel<<<M_, 256>>>(qw, cosh_, sinh_);
    knorm_rope_v_kernel<<<M_, 256>>>(kw, cosh_, sinh_);

    // attention (raw mma.sync, QT=128)
    attn_kernel<<<dim3(S_ / QT2, H_, B_), 256, ATT_SMEM_BYTES>>>();

    // output projection
    gemm_f16<<<dim3(DIM_ / 128, M_ / 128), 256, GEMM_SMEM>>>(p_attn, p_wo, out, DIM_, DIM_);
}